// round 1
// baseline (speedup 1.0000x reference)
#include <cuda_runtime.h>
#include <math.h>

#define T_DIM 16
#define B_DIM 512
#define E_DIM 256
#define V_DIM 25
#define NPAIR (T_DIM * B_DIM * V_DIM)   // 204800 (t,b,v) sites
#define RED_BLOCKS 256

// Scratch (no allocations allowed): per-block double partials + per-channel coefs.
__device__ double d_part[RED_BLOCKS][5];
__device__ float4 d_A[E_DIM];   // {w0, w1, mean, rstd}
__device__ float2 d_G[E_DIM];   // {gamma, beta}

// ---------------------------------------------------------------------------
// Kernel 1: 5 moments of x over all (t,b,v): E[x0],E[x1],E[x0^2],E[x1^2],E[x0*x1]
// x layout: [T,B,C,V] -> per (t,b): 50 contiguous floats (c0: 0..24, c1: 25..49)
// ---------------------------------------------------------------------------
__global__ void reduce_moments(const float* __restrict__ x) {
    double s0 = 0.0, s1 = 0.0, s2 = 0.0, s3 = 0.0, s4 = 0.0;
    int stride = gridDim.x * blockDim.x;
    for (int j = blockIdx.x * blockDim.x + threadIdx.x; j < NPAIR; j += stride) {
        int tb = j / V_DIM;
        int v  = j - tb * V_DIM;
        const float* base = x + tb * (2 * V_DIM);
        float x0 = base[v];
        float x1 = base[V_DIM + v];
        s0 += (double)x0;
        s1 += (double)x1;
        s2 += (double)x0 * (double)x0;
        s3 += (double)x1 * (double)x1;
        s4 += (double)x0 * (double)x1;
    }
    // warp reduce
    #pragma unroll
    for (int o = 16; o > 0; o >>= 1) {
        s0 += __shfl_down_sync(0xffffffffu, s0, o);
        s1 += __shfl_down_sync(0xffffffffu, s1, o);
        s2 += __shfl_down_sync(0xffffffffu, s2, o);
        s3 += __shfl_down_sync(0xffffffffu, s3, o);
        s4 += __shfl_down_sync(0xffffffffu, s4, o);
    }
    __shared__ double sh[8][5];
    int w = threadIdx.x >> 5, l = threadIdx.x & 31;
    if (l == 0) { sh[w][0] = s0; sh[w][1] = s1; sh[w][2] = s2; sh[w][3] = s3; sh[w][4] = s4; }
    __syncthreads();
    if (w == 0) {
        double t0 = (l < 8) ? sh[l][0] : 0.0;
        double t1 = (l < 8) ? sh[l][1] : 0.0;
        double t2 = (l < 8) ? sh[l][2] : 0.0;
        double t3 = (l < 8) ? sh[l][3] : 0.0;
        double t4 = (l < 8) ? sh[l][4] : 0.0;
        #pragma unroll
        for (int o = 4; o > 0; o >>= 1) {
            t0 += __shfl_down_sync(0xffffffffu, t0, o);
            t1 += __shfl_down_sync(0xffffffffu, t1, o);
            t2 += __shfl_down_sync(0xffffffffu, t2, o);
            t3 += __shfl_down_sync(0xffffffffu, t3, o);
            t4 += __shfl_down_sync(0xffffffffu, t4, o);
        }
        if (l == 0) {
            d_part[blockIdx.x][0] = t0;
            d_part[blockIdx.x][1] = t1;
            d_part[blockIdx.x][2] = t2;
            d_part[blockIdx.x][3] = t3;
            d_part[blockIdx.x][4] = t4;
        }
    }
}

// ---------------------------------------------------------------------------
// Kernel 2 (1 block, 256 threads): reduce partials, compute per-channel coefs.
// ---------------------------------------------------------------------------
__global__ void finalize_coefs(const float* __restrict__ W,
                               const float* __restrict__ gamma,
                               const float* __restrict__ beta) {
    __shared__ double tot[5];
    int tid = threadIdx.x;
    double s0 = d_part[tid][0];
    double s1 = d_part[tid][1];
    double s2 = d_part[tid][2];
    double s3 = d_part[tid][3];
    double s4 = d_part[tid][4];
    #pragma unroll
    for (int o = 16; o > 0; o >>= 1) {
        s0 += __shfl_down_sync(0xffffffffu, s0, o);
        s1 += __shfl_down_sync(0xffffffffu, s1, o);
        s2 += __shfl_down_sync(0xffffffffu, s2, o);
        s3 += __shfl_down_sync(0xffffffffu, s3, o);
        s4 += __shfl_down_sync(0xffffffffu, s4, o);
    }
    __shared__ double sh[8][5];
    int w = tid >> 5, l = tid & 31;
    if (l == 0) { sh[w][0] = s0; sh[w][1] = s1; sh[w][2] = s2; sh[w][3] = s3; sh[w][4] = s4; }
    __syncthreads();
    if (tid < 5) {
        double t = 0.0;
        #pragma unroll
        for (int i = 0; i < 8; i++) t += sh[i][tid];
        tot[tid] = t;
    }
    __syncthreads();

    const double invN = 1.0 / (double)NPAIR;
    double m0  = tot[0] * invN;
    double m1  = tot[1] * invN;
    double s00 = tot[2] * invN;
    double s11 = tot[3] * invN;
    double s01 = tot[4] * invN;

    int e = tid;
    float w0 = W[2 * e];
    float w1 = W[2 * e + 1];
    double mean = (double)w0 * m0 + (double)w1 * m1;
    double ey2  = (double)w0 * (double)w0 * s00
                + 2.0 * (double)w0 * (double)w1 * s01
                + (double)w1 * (double)w1 * s11;
    double var = ey2 - mean * mean;
    if (var < 0.0) var = 0.0;
    float rstd = (float)(1.0 / sqrt(var + 1e-5));
    d_A[e] = make_float4(w0, w1, (float)mean, rstd);
    d_G[e] = make_float2(gamma[e], beta[e]);
}

// ---------------------------------------------------------------------------
// Kernel 3: fused conv1x1 + BN + LIF scan. Block = (b, 64-channel chunk).
// Each thread owns float4 quads of the (e,v) plane; membrane state in regs.
// ---------------------------------------------------------------------------
__global__ void __launch_bounds__(128, 8)
lif_main(const float* __restrict__ x, float* __restrict__ out) {
    __shared__ float  xs[T_DIM][2 * V_DIM];  // x slice for this b: [16][50]
    __shared__ float4 As[64];
    __shared__ float2 Gs[64];

    int b  = blockIdx.x >> 2;
    int ec = blockIdx.x & 3;          // 64-channel chunk within E=256
    int tid = threadIdx.x;

    for (int i = tid; i < T_DIM * 2 * V_DIM; i += 128) {
        int t = i / (2 * V_DIM), r = i - t * (2 * V_DIM);
        xs[t][r] = x[(t * B_DIM + b) * (2 * V_DIM) + r];
    }
    if (tid < 64) {
        As[tid] = d_A[ec * 64 + tid];
        Gs[tid] = d_G[ec * 64 + tid];
    }
    __syncthreads();

    float4* o4 = reinterpret_cast<float4*>(out);
    // local plane for this chunk: 64*25 = 1600 elements = 400 float4 quads
    for (int q = tid; q < 400; q += 128) {
        int p = 4 * q;
        int vi[4];
        float w0[4], w1[4], mn[4], rs[4], ga[4], be[4];
        #pragma unroll
        for (int i = 0; i < 4; i++) {
            int pp = p + i;
            int e  = pp / V_DIM;
            vi[i]  = pp - e * V_DIM;
            float4 A = As[e];
            float2 G = Gs[e];
            w0[i] = A.x; w1[i] = A.y; mn[i] = A.z; rs[i] = A.w;
            ga[i] = G.x; be[i] = G.y;
        }
        float vs[4] = {0.f, 0.f, 0.f, 0.f};
        int base4 = b * (E_DIM * V_DIM / 4) + ec * 400 + q;
        #pragma unroll
        for (int t = 0; t < T_DIM; t++) {
            float4 sp4;
            float* spp = reinterpret_cast<float*>(&sp4);
            #pragma unroll
            for (int i = 0; i < 4; i++) {
                float x0 = xs[t][vi[i]];
                float x1 = xs[t][V_DIM + vi[i]];
                float y  = fmaf(x0, w0[i], x1 * w1[i]);     // conv1x1 (K=2)
                float z  = (y - mn[i]) * rs[i];             // BN normalize
                float yn = fmaf(z, ga[i], be[i]);           // gamma/beta
                float vn = fmaf(yn - vs[i], 0.5f, vs[i]);   // v += (yn - v)/tau
                float sp = (vn >= 1.0f) ? 1.0f : 0.0f;      // threshold
                vs[i] = vn * (1.0f - sp);                   // hard reset
                spp[i] = sp;
            }
            o4[t * (B_DIM * E_DIM * V_DIM / 4) + base4] = sp4;
        }
    }
}

// ---------------------------------------------------------------------------
extern "C" void kernel_launch(void* const* d_in, const int* in_sizes, int n_in,
                              void* d_out, int out_size) {
    const float* x     = (const float*)d_in[0];
    const float* W     = (const float*)d_in[1];
    const float* gamma = (const float*)d_in[2];
    const float* beta  = (const float*)d_in[3];
    float* out = (float*)d_out;

    reduce_moments<<<RED_BLOCKS, 256>>>(x);
    finalize_coefs<<<1, 256>>>(W, gamma, beta);
    lif_main<<<B_DIM * 4, 128>>>(x, out);
}

// round 8
// speedup vs baseline: 1.0017x; 1.0017x over previous
#include <cuda_runtime.h>
#include <math.h>

#define T_DIM 16
#define B_DIM 512
#define E_DIM 256
#define V_DIM 25
#define NPAIR (T_DIM * B_DIM * V_DIM)   // 204800 (t,b,v) sites
#define RED_BLOCKS 256

// Scratch (no allocations allowed).
__device__ double d_part[RED_BLOCKS][5];
__device__ float4 d_A[E_DIM];           // {w0, w1, mean, rstd}  (R1-exact coefs)
__device__ float2 d_G[E_DIM];           // {gamma, beta}
__device__ unsigned int d_cnt = 0;      // last-block ticket; self-resets each call

// ---------------------------------------------------------------------------
// Kernel 1: 5 moments of x over all (t,b,v). Per-thread partial in fp32
// (~3 sites/thread), promoted to double for every reduction level so the
// final stats match the R1 all-double version to ~1e-9. Last-finishing block
// combines partials and emits per-channel {w0,w1,mean,rstd} + {gamma,beta}.
// x layout: [T,B,C,V] -> per (t,b): 50 contiguous floats (c0: 0..24, c1: 25..49)
// ---------------------------------------------------------------------------
__global__ void moments_and_coefs(const float* __restrict__ x,
                                  const float* __restrict__ W,
                                  const float* __restrict__ gamma,
                                  const float* __restrict__ beta) {
    float f0 = 0.f, f1 = 0.f, f2 = 0.f, f3 = 0.f, f4 = 0.f;
    int stride = gridDim.x * blockDim.x;
    for (int j = blockIdx.x * blockDim.x + threadIdx.x; j < NPAIR; j += stride) {
        int tb = j / V_DIM;
        int v  = j - tb * V_DIM;
        const float* base = x + tb * (2 * V_DIM);
        float x0 = base[v];
        float x1 = base[V_DIM + v];
        f0 += x0;
        f1 += x1;
        f2 = fmaf(x0, x0, f2);
        f3 = fmaf(x1, x1, f3);
        f4 = fmaf(x0, x1, f4);
    }
    // promote to double for all reduction levels
    double s0 = f0, s1 = f1, s2 = f2, s3 = f3, s4 = f4;
    #pragma unroll
    for (int o = 16; o > 0; o >>= 1) {
        s0 += __shfl_down_sync(0xffffffffu, s0, o);
        s1 += __shfl_down_sync(0xffffffffu, s1, o);
        s2 += __shfl_down_sync(0xffffffffu, s2, o);
        s3 += __shfl_down_sync(0xffffffffu, s3, o);
        s4 += __shfl_down_sync(0xffffffffu, s4, o);
    }
    __shared__ double sh[8][5];
    int w = threadIdx.x >> 5, l = threadIdx.x & 31;
    if (l == 0) { sh[w][0] = s0; sh[w][1] = s1; sh[w][2] = s2; sh[w][3] = s3; sh[w][4] = s4; }
    __syncthreads();
    if (threadIdx.x == 0) {
        double t0 = 0.0, t1 = 0.0, t2 = 0.0, t3 = 0.0, t4 = 0.0;
        #pragma unroll
        for (int i = 0; i < 8; i++) {
            t0 += sh[i][0]; t1 += sh[i][1]; t2 += sh[i][2]; t3 += sh[i][3]; t4 += sh[i][4];
        }
        d_part[blockIdx.x][0] = t0;
        d_part[blockIdx.x][1] = t1;
        d_part[blockIdx.x][2] = t2;
        d_part[blockIdx.x][3] = t3;
        d_part[blockIdx.x][4] = t4;
        __threadfence();
    }

    // last-block-done: the final block combines partials + computes coefs
    __shared__ bool isLast;
    if (threadIdx.x == 0) {
        unsigned int t = atomicAdd(&d_cnt, 1u);
        isLast = (t == (unsigned int)(RED_BLOCKS - 1));
    }
    __syncthreads();
    if (!isLast) return;

    double p0 = d_part[threadIdx.x][0];
    double p1 = d_part[threadIdx.x][1];
    double p2 = d_part[threadIdx.x][2];
    double p3 = d_part[threadIdx.x][3];
    double p4 = d_part[threadIdx.x][4];
    #pragma unroll
    for (int o = 16; o > 0; o >>= 1) {
        p0 += __shfl_down_sync(0xffffffffu, p0, o);
        p1 += __shfl_down_sync(0xffffffffu, p1, o);
        p2 += __shfl_down_sync(0xffffffffu, p2, o);
        p3 += __shfl_down_sync(0xffffffffu, p3, o);
        p4 += __shfl_down_sync(0xffffffffu, p4, o);
    }
    __shared__ double dsh[8][5];
    if (l == 0) { dsh[w][0] = p0; dsh[w][1] = p1; dsh[w][2] = p2; dsh[w][3] = p3; dsh[w][4] = p4; }
    __syncthreads();
    __shared__ double tot[5];
    if (threadIdx.x < 5) {
        double t = 0.0;
        #pragma unroll
        for (int i = 0; i < 8; i++) t += dsh[i][threadIdx.x];
        tot[threadIdx.x] = t;
    }
    __syncthreads();

    const double invN = 1.0 / (double)NPAIR;
    double m0  = tot[0] * invN;
    double m1  = tot[1] * invN;
    double s00 = tot[2] * invN;
    double s11 = tot[3] * invN;
    double s01 = tot[4] * invN;

    int e = threadIdx.x;
    float w0 = W[2 * e];
    float w1 = W[2 * e + 1];
    double mean = (double)w0 * m0 + (double)w1 * m1;
    double ey2  = (double)w0 * (double)w0 * s00
                + 2.0 * (double)w0 * (double)w1 * s01
                + (double)w1 * (double)w1 * s11;
    double var = ey2 - mean * mean;
    if (var < 0.0) var = 0.0;
    float rstd = (float)(1.0 / sqrt(var + 1e-5));
    d_A[e] = make_float4(w0, w1, (float)mean, rstd);
    d_G[e] = make_float2(gamma[e], beta[e]);

    if (threadIdx.x == 0) d_cnt = 0;  // reset for next graph replay
}

// ---------------------------------------------------------------------------
// Kernel 2: fused conv1x1 + BN + LIF scan. Block = one b (all 256 channels).
// 320 threads x 5 quads each = 1600 float4 quads of the [256,25] plane.
// Per-element arithmetic is IDENTICAL to the R1 passing kernel.
// x staged in shared as interleaved float2 -> 1 LDS.64 per element-step.
// Membrane state in registers across the unrolled t loop; streaming stores.
// ---------------------------------------------------------------------------
__global__ void __launch_bounds__(320, 4)
lif_main(const float* __restrict__ x, float* __restrict__ out) {
    __shared__ float2 xs2[T_DIM * V_DIM];  // [t][v] -> (x0, x1)
    __shared__ float4 As[E_DIM];
    __shared__ float2 Gs[E_DIM];

    int b   = blockIdx.x;
    int tid = threadIdx.x;

    // stage x: 400 (t,v) pairs
    for (int i = tid; i < T_DIM * V_DIM; i += 320) {
        int t = i / V_DIM, v = i - t * V_DIM;
        const float* base = x + (t * B_DIM + b) * (2 * V_DIM);
        xs2[i] = make_float2(base[v], base[V_DIM + v]);
    }
    if (tid < E_DIM) {
        As[tid] = d_A[tid];
        Gs[tid] = d_G[tid];
    }
    __syncthreads();

    float4* o4 = reinterpret_cast<float4*>(out);

    #pragma unroll 1
    for (int k = 0; k < 5; k++) {
        int q = tid + k * 320;          // quad index in [0,1600)
        int p = 4 * q;
        const float2* xb[4];
        float w0[4], w1[4], mn[4], rs[4], ga[4], be[4];
        #pragma unroll
        for (int i = 0; i < 4; i++) {
            int pp = p + i;
            int e  = pp / V_DIM;
            int v  = pp - e * V_DIM;
            float4 A = As[e];
            float2 G = Gs[e];
            w0[i] = A.x; w1[i] = A.y; mn[i] = A.z; rs[i] = A.w;
            ga[i] = G.x; be[i] = G.y;
            xb[i] = xs2 + v;            // + t*V_DIM folds into LDS immediate
        }
        float vs[4] = {0.f, 0.f, 0.f, 0.f};
        float4* op = o4 + b * (E_DIM * V_DIM / 4) + q;
        #pragma unroll
        for (int t = 0; t < T_DIM; t++) {
            float4 sp4;
            float* spp = reinterpret_cast<float*>(&sp4);
            #pragma unroll
            for (int i = 0; i < 4; i++) {
                float2 xv = xb[i][t * V_DIM];
                float y  = fmaf(xv.x, w0[i], xv.y * w1[i]);   // conv1x1 (K=2)
                float z  = (y - mn[i]) * rs[i];               // BN normalize
                float yn = fmaf(z, ga[i], be[i]);             // gamma/beta
                float vn = fmaf(yn - vs[i], 0.5f, vs[i]);     // v += (yn - v)/tau
                float sp = (vn >= 1.0f) ? 1.0f : 0.0f;        // threshold
                vs[i] = vn * (1.0f - sp);                     // hard reset
                spp[i] = sp;
            }
            __stcs(op, sp4);            // streaming store (write-once output)
            op += B_DIM * E_DIM * V_DIM / 4;
        }
    }
}

// ---------------------------------------------------------------------------
extern "C" void kernel_launch(void* const* d_in, const int* in_sizes, int n_in,
                              void* d_out, int out_size) {
    const float* x     = (const float*)d_in[0];
    const float* W     = (const float*)d_in[1];
    const float* gamma = (const float*)d_in[2];
    const float* beta  = (const float*)d_in[3];
    float* out = (float*)d_out;

    moments_and_coefs<<<RED_BLOCKS, 256>>>(x, W, gamma, beta);
    lif_main<<<B_DIM, 320>>>(x, out);
}